// round 15
// baseline (speedup 1.0000x reference)
#include <cuda_runtime.h>
#include <cuda_fp16.h>
#include <cstdint>

// Locally-connected 2D via single-pass fp16 mma.sync m16n8k16.
//   out[b,o,y,x] = sum_k patches[b,y,x,k] * W[y,x,o,k] + bias[y,x,o]
// x: [128,3,64,64] f32, W: [60,60,32,75] f32 (k = c*25+kh*5+kw),
// bias: [60,60,32] f32, out: [128,32,60,60] f32.
// R15: CTA = (py, 8 px guarded, half-batch 64). 256 thr, warp = position p,
// 64 acc/thread, 2 CTAs/SM. W staged raw f32 + in-loop cvt (R14). Stores:
// 8-px (32B) line-aligned runs, two lanes per row -> 16 lines per STG.128.

#define RYX  60
#define TX   8
#define XC   12          // TX + 4
#define NROW 180         // 15 * XC
#define SXS  72          // sXh row stride in u16 (64 + 8 pad)
#define NTHR 256

#define SW_OFF     25920                   // sXh = 180*72*2
#define BIAS_OFF   (SW_OFF + 76800)        // sW = 8*2400 f32 -> 102720
#define SMEM_TOTAL (BIAS_OFF + 1024)       // 103744 (sRep overlay 73728 fits)

#define W_FLOATS   (3600 * 2400)

__device__ unsigned short g_xh[3 * 64 * 64 * 128];   // fp16 x, [c][h][w][b]

// ---------------------------------------------------------------- helpers
__device__ __forceinline__ unsigned smem_u32(const void* p) {
    unsigned a;
    asm("{ .reg .u64 t; cvta.to.shared.u64 t, %1; cvt.u32.u64 %0, t; }" : "=r"(a) : "l"(p));
    return a;
}
__device__ __forceinline__ void cp16(unsigned sm, const void* g) {
    asm volatile("cp.async.cg.shared.global [%0], [%1], 16;"
                 :: "r"(sm), "l"(__cvta_generic_to_global(g)) : "memory");
}
__device__ __forceinline__ void cp_commit_wait() {
    asm volatile("cp.async.commit_group;" ::: "memory");
    asm volatile("cp.async.wait_group 0;" ::: "memory");
}
__device__ __forceinline__ int rcof(int k) {       // sXh row for flat k (pos 0)
    int c = k / 25, r = (k % 25) / 5, w = k % 5;
    return (c * 5 + r) * XC + w;
}
__device__ __forceinline__ unsigned pack_h2(float hi, float lo) {
    unsigned r;
    asm("cvt.rn.f16x2.f32 %0, %1, %2;" : "=r"(r) : "f"(hi), "f"(lo));
    return r;
}
__device__ __forceinline__ void mma_f16(float* d, const unsigned* a, unsigned b0, unsigned b1) {
    asm volatile(
        "mma.sync.aligned.m16n8k16.row.col.f32.f16.f16.f32 "
        "{%0,%1,%2,%3}, {%4,%5,%6,%7}, {%8,%9}, {%0,%1,%2,%3};"
        : "+f"(d[0]), "+f"(d[1]), "+f"(d[2]), "+f"(d[3])
        : "r"(a[0]), "r"(a[1]), "r"(a[2]), "r"(a[3]), "r"(b0), "r"(b1));
}

// ---------------------------------------------------------------- prep: x -> fp16 [c][h][w][b]
__global__ __launch_bounds__(256)
void prep_xh_kernel(const float* __restrict__ x)
{
    __shared__ float tile[32][33];
    const int wt    = blockIdx.x & 1;
    const int btile = blockIdx.x >> 1;
    const int h     = blockIdx.y;
    const int c     = blockIdx.z;
    const int tx = threadIdx.x, ty = threadIdx.y;

    #pragma unroll
    for (int j = 0; j < 4; j++) {
        int b = btile * 32 + ty + j * 8;
        tile[ty + j * 8][tx] =
            x[(((size_t)b * 3 + c) * 64 + h) * 64 + wt * 32 + tx];
    }
    __syncthreads();
    #pragma unroll
    for (int j = 0; j < 4; j++) {
        int w = wt * 32 + ty + j * 8;
        g_xh[(((size_t)c * 64 + h) * 64 + w) * 128 + btile * 32 + tx] =
            __half_as_ushort(__float2half_rn(tile[tx][ty + j * 8]));
    }
}

// ---------------------------------------------------------------- main
__global__ __launch_bounds__(NTHR, 2)
void lc2d_hmma_kernel(const float* __restrict__ W,
                      const float* __restrict__ bias,
                      float* __restrict__ out)
{
    extern __shared__ char smem[];
    unsigned short* sXh = (unsigned short*)smem;           // [180 rows][SXS]
    const float* sWf    = (const float*)(smem + SW_OFF);   // [8 pos][32 o][75] raw f32
    float* sBias        = (float*)(smem + BIAS_OFF);       // [8][32]

    const int xt    = blockIdx.x;         // 0..7
    const int py    = blockIdx.y;         // 0..59
    const int bhalf = blockIdx.z;         // 0,1
    const int px0   = xt * TX;
    const int pos0  = py * RYX + px0;
    const int tid   = threadIdx.x;

    const unsigned sXh_a = smem_u32(sXh);
    const unsigned sW_a  = smem_u32(sWf);

    // ---- stage x tile: 180 rows x 64 u16, cp.async 16B chunks ----
    for (int i = tid; i < NROW * 8; i += NTHR) {
        int q    = i & 7;
        int rc   = i >> 3;                 // (c*5+kh)*XC + col
        int crow = rc / XC, col = rc - crow * XC;
        int c = crow / 5, kh = crow - c * 5;
        int w = px0 + col; if (w > 63) w = 63;
        cp16(sXh_a + (rc * SXS + q * 8) * 2,
             &g_xh[(((size_t)c * 64 + py + kh) * 64 + w) * 128
                   + bhalf * 64 + q * 8]);
    }
    // ---- stage W raw: 8 positions x 2400 f32 contiguous (clamped at end) ----
    for (int i = tid; i < 4800; i += NTHR) {
        size_t goff = (size_t)pos0 * 2400 + (size_t)i * 4;
        if (goff > (size_t)W_FLOATS - 4) goff = (size_t)W_FLOATS - 4;
        cp16(sW_a + i * 16, W + goff);
    }
    if (tid < TX * 32) {
        int bi = pos0 * 32 + tid;
        if (bi > 3600 * 32 - 1) bi = 3600 * 32 - 1;
        sBias[tid] = bias[bi];
    }
    cp_commit_wait();
    __syncthreads();

    // ---- compute: warp = position p; 4 m-tiles (64 b) x 4 n-tiles (32 o) ----
    const int wid  = tid >> 5;
    const int lane = tid & 31;
    const int gid  = lane >> 2;
    const int tg   = lane & 3;
    const int p    = wid;               // 0..7

    float acc[4][4][4];
    #pragma unroll
    for (int mt = 0; mt < 4; mt++)
        #pragma unroll
        for (int nt = 0; nt < 4; nt++)
            #pragma unroll
            for (int r = 0; r < 4; r++) acc[mt][nt][r] = 0.0f;

    const float* wrow = sWf + (p * 32 + gid) * 75;   // + nt*600 + k

    #pragma unroll
    for (int s = 0; s < 5; s++) {
        const int k0 = 16 * s + 2 * tg;

        // B fragments from raw W: LDS + cvt
        uint2 bh[4];
        #pragma unroll
        for (int nt = 0; nt < 4; nt++) {
            const float* wr = wrow + nt * 600;
            float f0 = wr[k0];
            float f1 = wr[k0 + 1];
            float f2, f3;
            if (s < 4) {
                f2 = wr[k0 + 8];
                f3 = wr[k0 + 9];
            } else {
                f2 = (k0 + 8 < 75) ? wr[k0 + 8] : 0.0f;
                f3 = (k0 + 9 < 75) ? wr[k0 + 9] : 0.0f;
            }
            bh[nt].x = pack_h2(f1, f0);
            bh[nt].y = pack_h2(f3, f2);
        }

        // A row offsets (u16 index) for k0, k0+1, k0+8, k0+9
        const int off00 = (rcof(k0)     + p) * SXS;
        const int off01 = (rcof(k0 + 1) + p) * SXS;
        const bool v2 = (k0 + 8) < 75;
        const bool v3 = (k0 + 9) < 75;
        const int off10 = v2 ? (rcof(k0 + 8) + p) * SXS : 0;
        const int off11 = v3 ? (rcof(k0 + 9) + p) * SXS : 0;

        #pragma unroll
        for (int mt = 0; mt < 4; mt++) {
            const int b = mt * 16 + gid;
            unsigned a[4];
            a[0] = (unsigned)sXh[off00 + b]
                 | ((unsigned)sXh[off01 + b] << 16);
            a[1] = (unsigned)sXh[off00 + b + 8]
                 | ((unsigned)sXh[off01 + b + 8] << 16);
            a[2] = (v2 ? (unsigned)sXh[off10 + b] : 0u)
                 | ((v3 ? (unsigned)sXh[off11 + b] : 0u) << 16);
            a[3] = (v2 ? (unsigned)sXh[off10 + b + 8] : 0u)
                 | ((v3 ? (unsigned)sXh[off11 + b + 8] : 0u) << 16);

            #pragma unroll
            for (int nt = 0; nt < 4; nt++)
                mma_f16(acc[mt][nt], a, bh[nt].x, bh[nt].y);
        }
    }

    // ---- bias into regs, then overlay stage with repack buffer ----
    float bsv[4][2];
    #pragma unroll
    for (int nt = 0; nt < 4; nt++) {
        bsv[nt][0] = sBias[p * 32 + nt * 8 + 2 * tg];
        bsv[nt][1] = sBias[p * 32 + nt * 8 + 2 * tg + 1];
    }
    __syncthreads();   // sXh + sW dead

    // ---- repack: sRep[row*9 + ((p + b') & 7)], row = b'*32 + o (b' 0..63) ----
    float* sRep = (float*)smem;          // [2048][9]
    #pragma unroll
    for (int mt = 0; mt < 4; mt++) {
        #pragma unroll
        for (int rh = 0; rh < 2; rh++) {
            const int bb  = mt * 16 + gid + rh * 8;
            const int col = (p + bb) & 7;
            #pragma unroll
            for (int nt = 0; nt < 4; nt++) {
                const int o = nt * 8 + 2 * tg;
                sRep[(bb * 32 + o)     * 9 + col] = acc[mt][nt][rh * 2]     + bsv[nt][0];
                sRep[(bb * 32 + o + 1) * 9 + col] = acc[mt][nt][rh * 2 + 1] + bsv[nt][1];
            }
        }
    }
    __syncthreads();

    // ---- store: two lanes per row (two float4 halves of a 32B run) ----
    const int vx8 = (px0 + TX <= RYX);    // 0 on xt==7 (only 4 valid px)
    #pragma unroll
    for (int it = 0; it < 16; it++) {
        const int u    = it * NTHR + tid;    // 0..4095
        const int row  = u >> 1;             // b'*32 + o
        const int half = u & 1;
        if (half && !vx8) continue;
        const int rot = (row >> 5) & 7;
        float v[4];
        #pragma unroll
        for (int i = 0; i < 4; i++)
            v[i] = sRep[row * 9 + ((4 * half + i + rot) & 7)];
        const size_t rg = (size_t)(bhalf * 2048 + row);
        *reinterpret_cast<float4*>(&out[rg * 3600 + pos0 + 4 * half]) =
            make_float4(v[0], v[1], v[2], v[3]);
    }
}

// ---------------------------------------------------------------- launch
extern "C" void kernel_launch(void* const* d_in, const int* in_sizes, int n_in,
                              void* d_out, int out_size)
{
    const float* x    = (const float*)d_in[0];
    const float* W    = (const float*)d_in[1];
    const float* bias = (const float*)d_in[2];
    float* out        = (float*)d_out;

    cudaFuncSetAttribute(lc2d_hmma_kernel,
                         cudaFuncAttributeMaxDynamicSharedMemorySize, SMEM_TOTAL);

    prep_xh_kernel<<<dim3(8, 64, 3), dim3(32, 8)>>>(x);
    lc2d_hmma_kernel<<<dim3(8, RYX, 2), NTHR, SMEM_TOTAL>>>(W, bias, out);
}